// round 15
// baseline (speedup 1.0000x reference)
#include <cuda_runtime.h>
#include <cuda_fp16.h>
#include <cstdint>

#define EN    262144
#define MROWS 64
#define NCTA  (EN / MROWS)   // 4096
#define NTH   256

// ---------- frag-packed fp16 weights ----------
// W1: 12 tiles (chunk*6+slice), tile=[64k x 256n] fp16 = 32KB
__device__ __align__(128) unsigned char g_W1p[12 * 32768];   // 384 KB
// W2: 8 quarter-tiles of [64k x 128n] = 16KB (global k-slice order)
__device__ __align__(128) unsigned char g_W2p[8 * 16384];    // 128 KB

// ---------- smem layout (per 64-row CTA, 113KB -> 2 CTAs/SM) ----------
// hdr mbars: fullW1b0@0 fullW1b1@8 w2A@16 w2B@24
#define SM_A    1024        // 6 resident A-frag slices x 8KB = 48KB
#define SM_R    50176       // 64KB region: W1 b0 (32KB) + W1 b1 (32KB)
                            // GEMM2: H (32KB) in b0; W2 quarters A/B in b1 halves
#define SM_TOT  115712

// ---------- PTX helpers ----------
__device__ __forceinline__ uint32_t smem_u32(const void* p) {
    uint32_t a;
    asm("{ .reg .u64 t; cvta.to.shared.u64 t, %1; cvt.u32.u64 %0, t; }" : "=r"(a) : "l"(p));
    return a;
}
#define MBAR_INIT(a, n)   asm volatile("mbarrier.init.shared.b64 [%0], %1;" :: "r"(a), "r"(n) : "memory")
#define MBAR_EXPECT(a, b) asm volatile("mbarrier.arrive.expect_tx.shared.b64 _, [%0], %1;" :: "r"(a), "r"(b) : "memory")
#define MBAR_WAIT(a, ph) do { \
    uint32_t _m = (a), _p = (ph), _d; \
    asm volatile("{ .reg .pred p; mbarrier.try_wait.parity.acquire.cta.shared::cta.b64 p, [%1], %2; selp.b32 %0,1,0,p; }" \
        : "=r"(_d) : "r"(_m), "r"(_p) : "memory"); \
    if (!_d) { \
        asm volatile("{ .reg .pred P1; WL_%=: mbarrier.try_wait.parity.acquire.cta.shared::cta.b64 P1, [%0], %1, 0x989680;\n\t" \
                     "@P1 bra.uni WD_%=; bra.uni WL_%=; WD_%=: }" :: "r"(_m), "r"(_p) : "memory"); \
    } } while (0)

__device__ __forceinline__ void bulk_g2s(uint32_t dst, const void* src, uint32_t bytes, uint32_t bar) {
    asm volatile("cp.async.bulk.shared::cluster.global.mbarrier::complete_tx::bytes [%0], [%1], %2, [%3];"
        :: "r"(dst), "l"(src), "r"(bytes), "r"(bar) : "memory");
}
__device__ __forceinline__ uint32_t pack2h(float v0, float v1) {
    uint32_t r;
    asm("cvt.rn.f16x2.f32 %0, %1, %2;" : "=r"(r) : "f"(v1), "f"(v0));
    return r;
}
__device__ __forceinline__ void mma_f16(float* c, const uint4& a, uint32_t b0, uint32_t b1) {
    asm volatile("mma.sync.aligned.m16n8k16.row.col.f32.f16.f16.f32 "
        "{%0,%1,%2,%3}, {%4,%5,%6,%7}, {%8,%9}, {%0,%1,%2,%3};"
        : "+f"(c[0]), "+f"(c[1]), "+f"(c[2]), "+f"(c[3])
        : "r"(a.x), "r"(a.y), "r"(a.z), "r"(a.w), "r"(b0), "r"(b1));
}

// ---------- pack kernel ----------
__global__ void pack_w(const float* __restrict__ W1, const float* __restrict__ W2) {
    int idx = blockIdx.x * blockDim.x + threadIdx.x;
    if (idx < 98304) {           // W1: kp*512 + n  (N=256 chunks)
        int kp = idx >> 9, n = idx & 511, k = kp * 2;
        float v0 = W1[(size_t)k * 512 + n], v1 = W1[(size_t)(k + 1) * 512 + n];
        int chunk = n >> 8, slice = k >> 6;
        int kt = (k & 63) >> 4, reg = (k & 15) >> 3;
        int np = (n & 255) >> 4, sub = (n >> 3) & 1;
        int lane = (n & 7) * 4 + ((k & 7) >> 1);
        size_t off = (size_t)(chunk * 6 + slice) * 32768
                   + (size_t)((kt * 16 + np) * 32 + lane) * 16 + sub * 8 + reg * 4;
        *(uint32_t*)(g_W1p + off) = pack2h(v0, v1);
    } else {                     // W2: kp*128 + n  (16KB quarter per global k-slice)
        int j = idx - 98304;
        int kp = j >> 7, n = j & 127, k = kp * 2;
        float v0 = W2[(size_t)k * 128 + n], v1 = W2[(size_t)(k + 1) * 128 + n];
        int q = k >> 6;                       // global k-slice 0..7
        int kt = (k & 63) >> 4, reg = (k & 15) >> 3;
        int nt = n >> 3, np = nt >> 1, sub = nt & 1;
        int lane = (n & 7) * 4 + ((k & 7) >> 1);
        size_t off = (size_t)q * 16384
                   + (size_t)((kt * 8 + np) * 32 + lane) * 16 + sub * 8 + reg * 4;
        *(uint32_t*)(g_W2p + off) = pack2h(v0, v1);
    }
}

// ---------- main kernel: 64 rows / 256 threads / 2 CTAs per SM ----------
__global__ void __launch_bounds__(NTH, 2) edge_mlp_hmma(
    const float* __restrict__ x_i, const float* __restrict__ x_j,
    const float* __restrict__ edge,
    const float* __restrict__ b1, const float* __restrict__ b2,
    const float* __restrict__ gamma, const float* __restrict__ beta,
    float* __restrict__ out)
{
    extern __shared__ char smem[];
    const uint32_t sb = smem_u32(smem);
    const int tid  = threadIdx.x;
    const int w    = tid >> 5, lane = tid & 31;
    const int mband = w >> 2, nband = w & 3;      // 2 mbands x 4 nbands
    const int row0 = blockIdx.x * MROWS;

    if (tid == 0) {
        MBAR_INIT(sb + 0, 1);    // full W1 buf0 (tx)
        MBAR_INIT(sb + 8, 1);    // full W1 buf1 (tx)
        MBAR_INIT(sb + 16, 1);   // W2 buffer A (tx)
        MBAR_INIT(sb + 24, 1);   // W2 buffer B (tx)
    }
    __syncthreads();

    float acc1[2][8][4];   // 2 m-tiles x 8 n-tiles (warp tile 32x64)
    float acc2[2][4][4];
#pragma unroll
    for (int a = 0; a < 2; a++) {
#pragma unroll
        for (int b = 0; b < 8; b++)
#pragma unroll
            for (int cc = 0; cc < 4; cc++) acc1[a][b][cc] = 0.f;
#pragma unroll
        for (int b = 0; b < 4; b++)
#pragma unroll
            for (int cc = 0; cc < 4; cc++) acc2[a][b][cc] = 0.f;
    }

    int p0 = 0, p1 = 0, pwa = 0, pwb = 0;

    // per-warp frag address bases
    const uint32_t afr0 = (uint32_t)((mband * 2) * 4) * 512 + (uint32_t)lane * 16;
    const uint32_t afr1 = (uint32_t)((mband * 2 + 1) * 4) * 512 + (uint32_t)lane * 16;
    const uint32_t hfr0 = (uint32_t)((mband * 2) * 16) * 512 + (uint32_t)lane * 16;
    const uint32_t hfr1 = (uint32_t)((mband * 2 + 1) * 16) * 512 + (uint32_t)lane * 16;

    // conversion geometry: entries e=tid, e=tid+256
    const int e0mt = tid >> 7, e0kt = (tid >> 5) & 3, eln = tid & 31;
    const int r0a = e0mt * 16 + (eln >> 2);
    const int r0b = (e0mt + 2) * 16 + (eln >> 2);
    const int c0a = e0kt * 16 + (eln & 3) * 2;

    // ---- prologue: W1 tile 0 -> buf0; convert ALL 6 A-slices (resident) ----
    if (tid == 0) { MBAR_EXPECT(sb + 0, 32768); bulk_g2s(sb + SM_R, g_W1p, 32768, sb + 0); }
#pragma unroll 1
    for (int ss = 0; ss < 6; ss++) {
        const float* xs = (ss < 2) ? x_i : (ss < 4) ? x_j : edge;
        const int koff = (ss & 1) * 64;
        char* Ab = smem + SM_A + ss * 8192;
        float2 v[8];
#pragma unroll
        for (int ee = 0; ee < 2; ee++) {
            int rr = ee ? r0b : r0a;
            const float* base = xs + (size_t)(row0 + rr) * 128 + koff + c0a;
            v[ee * 4 + 0] = *(const float2*)(base);
            v[ee * 4 + 1] = *(const float2*)(base + 8 * 128);
            v[ee * 4 + 2] = *(const float2*)(base + 8);
            v[ee * 4 + 3] = *(const float2*)(base + 8 * 128 + 8);
        }
#pragma unroll
        for (int ee = 0; ee < 2; ee++) {
            uint4 hv;
            hv.x = pack2h(v[ee * 4 + 0].x, v[ee * 4 + 0].y);
            hv.y = pack2h(v[ee * 4 + 1].x, v[ee * 4 + 1].y);
            hv.z = pack2h(v[ee * 4 + 2].x, v[ee * 4 + 2].y);
            hv.w = pack2h(v[ee * 4 + 3].x, v[ee * 4 + 3].y);
            *(uint4*)(Ab + (uint32_t)(tid + ee * 256) * 16) = hv;
        }
    }
    __syncthreads();

    // A-frag register ring, primed with slice 0 / kt 0 (A is resident: loads
    // never depend on barriers, so the ring legally spans slice boundaries)
    uint4 ah[2][2];
    ah[0][0] = *(const uint4*)(smem + SM_A + afr0);
    ah[0][1] = *(const uint4*)(smem + SM_A + afr1);

#pragma unroll 1
    for (int c = 0; c < 2; c++) {
        // ===== GEMM1: 6 k-slices, N=256, 2x32KB ring, A reg-pipelined =====
#pragma unroll 1
        for (int sl = 0; sl < 6; sl++) {
            if (tid == 0) {
                if (sl & 1) { MBAR_WAIT(sb + 8, p1); p1 ^= 1; }
                else        { MBAR_WAIT(sb + 0, p0); p0 ^= 1; }
            }
            __syncthreads();   // W1(sl) visible; MMA(sl-1) done -> other buf free
            if (tid == 0 && sl < 5) {
                const int b = (sl + 1) & 1;
                MBAR_EXPECT(sb + b * 8, 32768);
                bulk_g2s(sb + SM_R + b * 32768, g_W1p + (size_t)(c * 6 + sl + 1) * 32768, 32768, sb + b * 8);
            }
            const char* Wb = smem + SM_R + (sl & 1) * 32768;
#pragma unroll
            for (int kt = 0; kt < 4; kt++) {
                const int cb = kt & 1, nb = cb ^ 1;
                {   // prefetch A frags for kt+1 (kt==3: next slice's kt0; wraps mod 6)
                    const int nsl = (kt < 3) ? sl : ((sl + 1) % 6);
                    const int nkt = (kt + 1) & 3;
                    const char* An = smem + SM_A + nsl * 8192;
                    ah[nb][0] = *(const uint4*)(An + afr0 + (uint32_t)nkt * 512);
                    ah[nb][1] = *(const uint4*)(An + afr1 + (uint32_t)nkt * 512);
                }
#pragma unroll
                for (int j = 0; j < 4; j++) {
                    uint4 Bv = *(const uint4*)(Wb + (uint32_t)((kt * 16 + nband * 4 + j) * 512) + (uint32_t)lane * 16);
                    mma_f16(acc1[0][2 * j],     ah[cb][0], Bv.x, Bv.y);
                    mma_f16(acc1[1][2 * j],     ah[cb][1], Bv.x, Bv.y);
                    mma_f16(acc1[0][2 * j + 1], ah[cb][0], Bv.z, Bv.w);
                    mma_f16(acc1[1][2 * j + 1], ah[cb][1], Bv.z, Bv.w);
                }
            }
        }

        // ===== post-GEMM1: issue W2 q0->A, q1->B; write H (32KB) -> b0 =====
        __syncthreads();   // slice-5 MMAs done: both bufs reusable
        if (tid == 0) {
            MBAR_EXPECT(sb + 16, 16384);
            bulk_g2s(sb + SM_R + 32768, g_W2p + (size_t)(c * 4) * 16384, 16384, sb + 16);
            MBAR_EXPECT(sb + 24, 16384);
            bulk_g2s(sb + SM_R + 49152, g_W2p + (size_t)(c * 4 + 1) * 16384, 16384, sb + 24);
        }
        // H write: SiLU(acc1+b1) as A-frags [64r x 256k] into b0
#pragma unroll
        for (int mtp = 0; mtp < 2; mtp++) {
#pragma unroll
            for (int j = 0; j < 4; j++) {
                const int kq = nband * 4 + j;
                const int colg = c * 256 + nband * 64 + j * 16 + (lane & 3) * 2;
                const float b00 = b1[colg],     b01 = b1[colg + 1];
                const float b10 = b1[colg + 8], b11 = b1[colg + 9];
                float v0 = acc1[mtp][2 * j][0] + b00;
                float v1 = acc1[mtp][2 * j][1] + b01;
                float v2 = acc1[mtp][2 * j][2] + b00;
                float v3 = acc1[mtp][2 * j][3] + b01;
                float w0 = acc1[mtp][2 * j + 1][0] + b10;
                float w1 = acc1[mtp][2 * j + 1][1] + b11;
                float w2 = acc1[mtp][2 * j + 1][2] + b10;
                float w3 = acc1[mtp][2 * j + 1][3] + b11;
                v0 /= (1.0f + __expf(-v0)); v1 /= (1.0f + __expf(-v1));
                v2 /= (1.0f + __expf(-v2)); v3 /= (1.0f + __expf(-v3));
                w0 /= (1.0f + __expf(-w0)); w1 /= (1.0f + __expf(-w1));
                w2 /= (1.0f + __expf(-w2)); w3 /= (1.0f + __expf(-w3));
                uint4 hv;
                hv.x = pack2h(v0, v1); hv.y = pack2h(v2, v3);
                hv.z = pack2h(w0, w1); hv.w = pack2h(w2, w3);
                const uint32_t hb = (uint32_t)(((mband * 2 + mtp) * 16 + kq) * 512) + (uint32_t)lane * 16;
                *(uint4*)(smem + SM_R + hb) = hv;
            }
        }

        // ===== GEMM2: 4 phases of k=64; W2 ping-pong A/B; H reg-pipelined =====
        uint4 hh[2][2];
#pragma unroll 1
        for (int p = 0; p < 4; p++) {
            const int bsel = p & 1;      // A for p=0,2 ; B for p=1,3
            if (tid == 0) {
                if (bsel) { MBAR_WAIT(sb + 24, pwb); pwb ^= 1; }
                else      { MBAR_WAIT(sb + 16, pwa); pwa ^= 1; }
            }
            __syncthreads();   // quarter visible; phase p-1 MMAs done; p==0: H visible
            if (tid == 0 && (p == 1 || p == 2)) {   // p=1: q2->A ; p=2: q3->B
                uint32_t bar = sb + ((p == 1) ? 16 : 24);
                uint32_t dst = sb + SM_R + 32768 + ((p == 1) ? 0 : 16384);
                MBAR_EXPECT(bar, 16384);
                bulk_g2s(dst, g_W2p + (size_t)(c * 4 + 1 + p) * 16384, 16384, bar);
            }
            const char* Hb = smem + SM_R;
            const char* Wq = smem + SM_R + 32768 + bsel * 16384;
            if (p == 0) {      // prime H ring with st=0 (after sync: H visible)
                hh[0][0] = *(const uint4*)(Hb + hfr0);
                hh[0][1] = *(const uint4*)(Hb + hfr1);
            }
#pragma unroll
            for (int kt = 0; kt < 4; kt++) {
                const int st = p * 4 + kt;
                const int cb = st & 1, nb = cb ^ 1;
                {   // prefetch H frags for st+1 (wrap &15 harmless; re-primed at p==0)
                    const int nst = (st + 1) & 15;
                    hh[nb][0] = *(const uint4*)(Hb + hfr0 + (uint32_t)nst * 512);
                    hh[nb][1] = *(const uint4*)(Hb + hfr1 + (uint32_t)nst * 512);
                }
#pragma unroll
                for (int np = 0; np < 2; np++) {
                    uint4 Bv = *(const uint4*)(Wq + (uint32_t)(((kt * 8 + nband * 2 + np) * 32 + lane) * 16));
                    mma_f16(acc2[0][np * 2],     hh[cb][0], Bv.x, Bv.y);
                    mma_f16(acc2[1][np * 2],     hh[cb][1], Bv.x, Bv.y);
                    mma_f16(acc2[0][np * 2 + 1], hh[cb][0], Bv.z, Bv.w);
                    mma_f16(acc2[1][np * 2 + 1], hh[cb][1], Bv.z, Bv.w);
                }
            }
        }
        __syncthreads();   // phase3 done: H/b0 and b1 free
        if (tid == 0 && c == 0) {          // next chunk's W1 tile 0 -> buf0
            MBAR_EXPECT(sb + 0, 32768);
            bulk_g2s(sb + SM_R, g_W1p + (size_t)6 * 32768, 32768, sb + 0);
        }
        // reset acc1 for next chunk
#pragma unroll
        for (int a = 0; a < 2; a++)
#pragma unroll
            for (int b = 0; b < 8; b++)
#pragma unroll
                for (int cc = 0; cc < 4; cc++) acc1[a][b][cc] = 0.f;
    }

    // ===== epilogue: stage acc2+b2 (overlay A region), LayerNorm, +edge, store =====
    float* stg = (float*)(smem + SM_A);   // 64 x 130 fp32
#pragma unroll
    for (int ntp = 0; ntp < 4; ntp++) {
        int col = nband * 32 + ntp * 8 + (lane & 3) * 2;
        float bb0 = b2[col], bb1 = b2[col + 1];
#pragma unroll
        for (int mtp = 0; mtp < 2; mtp++) {
            int row = mband * 32 + mtp * 16 + (lane >> 2);
            float2 v0 = make_float2(acc2[mtp][ntp][0] + bb0, acc2[mtp][ntp][1] + bb1);
            float2 v1 = make_float2(acc2[mtp][ntp][2] + bb0, acc2[mtp][ntp][3] + bb1);
            *(float2*)(stg + row * 130 + col)       = v0;
            *(float2*)(stg + (row + 8) * 130 + col) = v1;
        }
    }
    __syncthreads();
    if (tid < MROWS) {
        float* rp = stg + tid * 130;
        float s = 0.f, qq = 0.f;
#pragma unroll
        for (int j = 0; j < 128; j += 2) {
            float2 v = *(float2*)(rp + j);
            s += v.x + v.y;
            qq += v.x * v.x + v.y * v.y;
        }
        float mu = s * (1.0f / 128.0f);
        float var = qq * (1.0f / 128.0f) - mu * mu;
        float rs = rsqrtf(var + 1e-5f);
#pragma unroll
        for (int j = 0; j < 128; j += 2) {
            float2 v = *(float2*)(rp + j);
            float2 g = *(const float2*)(gamma + j);
            float2 b = *(const float2*)(beta + j);
            v.x = (v.x - mu) * rs * g.x + b.x;
            v.y = (v.y - mu) * rs * g.y + b.y;
            *(float2*)(rp + j) = v;
        }
    }
    __syncthreads();
#pragma unroll
    for (int it = 0; it < 8; it++) {
        int idx = tid + it * NTH;
        int r = idx >> 5, c4 = idx & 31;
        float2 u0 = *(float2*)(stg + r * 130 + c4 * 4);
        float2 u1 = *(float2*)(stg + r * 130 + c4 * 4 + 2);
        float4 e = *(const float4*)(edge + (size_t)(row0 + r) * 128 + c4 * 4);
        float4 o = make_float4(u0.x + e.x, u0.y + e.y, u1.x + e.z, u1.y + e.w);
        *(float4*)(out + (size_t)(row0 + r) * 128 + c4 * 4) = o;
    }
}

extern "C" void kernel_launch(void* const* d_in, const int* in_sizes, int n_in,
                              void* d_out, int out_size)
{
    const float* x_i   = (const float*)d_in[0];
    const float* x_j   = (const float*)d_in[1];
    const float* edge  = (const float*)d_in[2];
    const float* W1    = (const float*)d_in[3];
    const float* b1    = (const float*)d_in[4];
    const float* W2    = (const float*)d_in[5];
    const float* b2    = (const float*)d_in[6];
    const float* gamma = (const float*)d_in[7];
    const float* beta  = (const float*)d_in[8];
    float* out = (float*)d_out;

    cudaFuncSetAttribute(edge_mlp_hmma, cudaFuncAttributeMaxDynamicSharedMemorySize, SM_TOT);

    pack_w<<<512, 256>>>(W1, W2);
    edge_mlp_hmma<<<NCTA, NTH, SM_TOT>>>(x_i, x_j, edge, b1, b2, gamma, beta, out);
}

// round 16
// speedup vs baseline: 1.0726x; 1.0726x over previous
#include <cuda_runtime.h>
#include <cuda_fp16.h>
#include <cstdint>

#define EN    262144
#define MROWS 64
#define NCTA  (EN / MROWS)   // 4096
#define NTH   256

// ---------- frag-packed fp16 weights ----------
// W1: 12 tiles (chunk*6+slice), tile=[64k x 256n] fp16 = 32KB
__device__ __align__(128) unsigned char g_W1p[12 * 32768];   // 384 KB
// W2: 8 quarter-tiles of [64k x 128n] = 16KB (global k-slice order)
__device__ __align__(128) unsigned char g_W2p[8 * 16384];    // 128 KB

// ---------- smem layout (per 64-row CTA, 113KB -> 2 CTAs/SM) ----------
// hdr mbars: fullW1b0@0 fullW1b1@8 w2A@16 w2B@24
#define SM_A    1024        // 6 resident A-frag slices x 8KB = 48KB
                            // (c==1 GEMM2: holds W2 q6/q7 — A is dead there;
                            //  epilogue staging overlays it after the final sync)
#define SM_R    50176       // 64KB region: W1 b0 (32KB) + W1 b1 (32KB)
                            // GEMM2: H (32KB) in b0; W2 quarters A/B in b1 halves
#define SM_TOT  115712

// ---------- PTX helpers ----------
__device__ __forceinline__ uint32_t smem_u32(const void* p) {
    uint32_t a;
    asm("{ .reg .u64 t; cvta.to.shared.u64 t, %1; cvt.u32.u64 %0, t; }" : "=r"(a) : "l"(p));
    return a;
}
#define MBAR_INIT(a, n)   asm volatile("mbarrier.init.shared.b64 [%0], %1;" :: "r"(a), "r"(n) : "memory")
#define MBAR_EXPECT(a, b) asm volatile("mbarrier.arrive.expect_tx.shared.b64 _, [%0], %1;" :: "r"(a), "r"(b) : "memory")
#define MBAR_WAIT(a, ph) do { \
    uint32_t _m = (a), _p = (ph), _d; \
    asm volatile("{ .reg .pred p; mbarrier.try_wait.parity.acquire.cta.shared::cta.b64 p, [%1], %2; selp.b32 %0,1,0,p; }" \
        : "=r"(_d) : "r"(_m), "r"(_p) : "memory"); \
    if (!_d) { \
        asm volatile("{ .reg .pred P1; WL_%=: mbarrier.try_wait.parity.acquire.cta.shared::cta.b64 P1, [%0], %1, 0x989680;\n\t" \
                     "@P1 bra.uni WD_%=; bra.uni WL_%=; WD_%=: }" :: "r"(_m), "r"(_p) : "memory"); \
    } } while (0)

__device__ __forceinline__ void bulk_g2s(uint32_t dst, const void* src, uint32_t bytes, uint32_t bar) {
    asm volatile("cp.async.bulk.shared::cluster.global.mbarrier::complete_tx::bytes [%0], [%1], %2, [%3];"
        :: "r"(dst), "l"(src), "r"(bytes), "r"(bar) : "memory");
}
__device__ __forceinline__ uint32_t pack2h(float v0, float v1) {
    uint32_t r;
    asm("cvt.rn.f16x2.f32 %0, %1, %2;" : "=r"(r) : "f"(v1), "f"(v0));
    return r;
}
__device__ __forceinline__ void mma_f16(float* c, const uint4& a, uint32_t b0, uint32_t b1) {
    asm volatile("mma.sync.aligned.m16n8k16.row.col.f32.f16.f16.f32 "
        "{%0,%1,%2,%3}, {%4,%5,%6,%7}, {%8,%9}, {%0,%1,%2,%3};"
        : "+f"(c[0]), "+f"(c[1]), "+f"(c[2]), "+f"(c[3])
        : "r"(a.x), "r"(a.y), "r"(a.z), "r"(a.w), "r"(b0), "r"(b1));
}

// ---------- pack kernel ----------
__global__ void pack_w(const float* __restrict__ W1, const float* __restrict__ W2) {
    int idx = blockIdx.x * blockDim.x + threadIdx.x;
    if (idx < 98304) {           // W1: kp*512 + n  (N=256 chunks)
        int kp = idx >> 9, n = idx & 511, k = kp * 2;
        float v0 = W1[(size_t)k * 512 + n], v1 = W1[(size_t)(k + 1) * 512 + n];
        int chunk = n >> 8, slice = k >> 6;
        int kt = (k & 63) >> 4, reg = (k & 15) >> 3;
        int np = (n & 255) >> 4, sub = (n >> 3) & 1;
        int lane = (n & 7) * 4 + ((k & 7) >> 1);
        size_t off = (size_t)(chunk * 6 + slice) * 32768
                   + (size_t)((kt * 16 + np) * 32 + lane) * 16 + sub * 8 + reg * 4;
        *(uint32_t*)(g_W1p + off) = pack2h(v0, v1);
    } else {                     // W2: kp*128 + n  (16KB quarter per global k-slice)
        int j = idx - 98304;
        int kp = j >> 7, n = j & 127, k = kp * 2;
        float v0 = W2[(size_t)k * 128 + n], v1 = W2[(size_t)(k + 1) * 128 + n];
        int q = k >> 6;                       // global k-slice 0..7
        int kt = (k & 63) >> 4, reg = (k & 15) >> 3;
        int nt = n >> 3, np = nt >> 1, sub = nt & 1;
        int lane = (n & 7) * 4 + ((k & 7) >> 1);
        size_t off = (size_t)q * 16384
                   + (size_t)((kt * 8 + np) * 32 + lane) * 16 + sub * 8 + reg * 4;
        *(uint32_t*)(g_W2p + off) = pack2h(v0, v1);
    }
}

// ---------- main kernel: 64 rows / 256 threads / 2 CTAs per SM ----------
__global__ void __launch_bounds__(NTH, 2) edge_mlp_hmma(
    const float* __restrict__ x_i, const float* __restrict__ x_j,
    const float* __restrict__ edge,
    const float* __restrict__ b1, const float* __restrict__ b2,
    const float* __restrict__ gamma, const float* __restrict__ beta,
    float* __restrict__ out)
{
    extern __shared__ char smem[];
    const uint32_t sb = smem_u32(smem);
    const int tid  = threadIdx.x;
    const int w    = tid >> 5, lane = tid & 31;
    const int mband = w >> 2, nband = w & 3;      // 2 mbands x 4 nbands
    const int row0 = blockIdx.x * MROWS;

    if (tid == 0) {
        MBAR_INIT(sb + 0, 1);    // full W1 buf0 (tx)
        MBAR_INIT(sb + 8, 1);    // full W1 buf1 (tx)
        MBAR_INIT(sb + 16, 1);   // W2 buffer A (tx)
        MBAR_INIT(sb + 24, 1);   // W2 buffer B (tx)
    }
    __syncthreads();

    float acc1[2][8][4];   // 2 m-tiles x 8 n-tiles (warp tile 32x64)
    float acc2[2][4][4];
#pragma unroll
    for (int a = 0; a < 2; a++) {
#pragma unroll
        for (int b = 0; b < 8; b++)
#pragma unroll
            for (int cc = 0; cc < 4; cc++) acc1[a][b][cc] = 0.f;
#pragma unroll
        for (int b = 0; b < 4; b++)
#pragma unroll
            for (int cc = 0; cc < 4; cc++) acc2[a][b][cc] = 0.f;
    }

    int p0 = 0, p1 = 0, pwa = 0, pwb = 0;

    // conversion geometry: entries e=tid, e=tid+256
    const int e0mt = tid >> 7, e0kt = (tid >> 5) & 3, eln = tid & 31;
    const int r0a = e0mt * 16 + (eln >> 2);
    const int r0b = (e0mt + 2) * 16 + (eln >> 2);
    const int c0a = e0kt * 16 + (eln & 3) * 2;

    // ---- prologue: W1 tile 0 -> buf0; convert ALL 6 A-slices (resident) ----
    if (tid == 0) { MBAR_EXPECT(sb + 0, 32768); bulk_g2s(sb + SM_R, g_W1p, 32768, sb + 0); }
#pragma unroll 1
    for (int ss = 0; ss < 6; ss++) {
        const float* xs = (ss < 2) ? x_i : (ss < 4) ? x_j : edge;
        const int koff = (ss & 1) * 64;
        char* Ab = smem + SM_A + ss * 8192;
        float2 v[8];
#pragma unroll
        for (int ee = 0; ee < 2; ee++) {
            int rr = ee ? r0b : r0a;
            const float* base = xs + (size_t)(row0 + rr) * 128 + koff + c0a;
            v[ee * 4 + 0] = *(const float2*)(base);
            v[ee * 4 + 1] = *(const float2*)(base + 8 * 128);
            v[ee * 4 + 2] = *(const float2*)(base + 8);
            v[ee * 4 + 3] = *(const float2*)(base + 8 * 128 + 8);
        }
#pragma unroll
        for (int ee = 0; ee < 2; ee++) {
            uint4 hv;
            hv.x = pack2h(v[ee * 4 + 0].x, v[ee * 4 + 0].y);
            hv.y = pack2h(v[ee * 4 + 1].x, v[ee * 4 + 1].y);
            hv.z = pack2h(v[ee * 4 + 2].x, v[ee * 4 + 2].y);
            hv.w = pack2h(v[ee * 4 + 3].x, v[ee * 4 + 3].y);
            *(uint4*)(Ab + (uint32_t)(tid + ee * 256) * 16) = hv;
        }
    }
    __syncthreads();

#pragma unroll 1
    for (int c = 0; c < 2; c++) {
        // ===== GEMM1: 6 k-slices, N=256, 2x32KB ring =====
#pragma unroll 1
        for (int sl = 0; sl < 6; sl++) {
            if (tid == 0) {
                if (sl & 1) { MBAR_WAIT(sb + 8, p1); p1 ^= 1; }
                else        { MBAR_WAIT(sb + 0, p0); p0 ^= 1; }
            }
            __syncthreads();   // W1(sl) visible; MMA(sl-1) done -> other buf free
            if (tid == 0 && sl < 5) {
                const int b = (sl + 1) & 1;
                MBAR_EXPECT(sb + b * 8, 32768);
                bulk_g2s(sb + SM_R + b * 32768, g_W1p + (size_t)(c * 6 + sl + 1) * 32768, 32768, sb + b * 8);
            }
            const char* Ab = smem + SM_A + sl * 8192;
            const char* Wb = smem + SM_R + (sl & 1) * 32768;
#pragma unroll
            for (int kt = 0; kt < 4; kt++) {
                uint4 ah0 = *(const uint4*)(Ab + (uint32_t)(((mband * 2) * 4 + kt) * 512) + (uint32_t)lane * 16);
                uint4 ah1 = *(const uint4*)(Ab + (uint32_t)(((mband * 2 + 1) * 4 + kt) * 512) + (uint32_t)lane * 16);
#pragma unroll
                for (int j = 0; j < 4; j++) {
                    uint4 Bv = *(const uint4*)(Wb + (uint32_t)((kt * 16 + nband * 4 + j) * 512) + (uint32_t)lane * 16);
                    mma_f16(acc1[0][2 * j],     ah0, Bv.x, Bv.y);
                    mma_f16(acc1[1][2 * j],     ah1, Bv.x, Bv.y);
                    mma_f16(acc1[0][2 * j + 1], ah0, Bv.z, Bv.w);
                    mma_f16(acc1[1][2 * j + 1], ah1, Bv.z, Bv.w);
                }
            }
        }

        // ===== post-GEMM1: issue W2 quarters; write H (32KB) -> b0 =====
        __syncthreads();   // slice-5 MMAs done: both bufs (and, for c==1, A) reusable
        if (tid == 0) {
            if (c == 0) {
                MBAR_EXPECT(sb + 16, 16384);
                bulk_g2s(sb + SM_R + 32768, g_W2p, 16384, sb + 16);
                MBAR_EXPECT(sb + 24, 16384);
                bulk_g2s(sb + SM_R + 49152, g_W2p + 16384, 16384, sb + 24);
            } else {
                // c==1: A region is dead -> load ALL four quarters now
                MBAR_EXPECT(sb + 16, 32768);
                bulk_g2s(sb + SM_R + 32768, g_W2p + (size_t)4 * 16384, 16384, sb + 16);  // q4 (p0)
                bulk_g2s(sb + SM_A,         g_W2p + (size_t)6 * 16384, 16384, sb + 16);  // q6 (p2)
                MBAR_EXPECT(sb + 24, 32768);
                bulk_g2s(sb + SM_R + 49152, g_W2p + (size_t)5 * 16384, 16384, sb + 24);  // q5 (p1)
                bulk_g2s(sb + SM_A + 16384, g_W2p + (size_t)7 * 16384, 16384, sb + 24);  // q7 (p3)
            }
        }
        // H write: this chunk's SiLU(acc1+b1) as A-frags [64r x 256k] into b0
#pragma unroll
        for (int mtp = 0; mtp < 2; mtp++) {
#pragma unroll
            for (int j = 0; j < 4; j++) {
                const int kq = nband * 4 + j;
                const int colg = c * 256 + nband * 64 + j * 16 + (lane & 3) * 2;
                const float b00 = b1[colg],     b01 = b1[colg + 1];
                const float b10 = b1[colg + 8], b11 = b1[colg + 9];
                float v0 = acc1[mtp][2 * j][0] + b00;
                float v1 = acc1[mtp][2 * j][1] + b01;
                float v2 = acc1[mtp][2 * j][2] + b00;
                float v3 = acc1[mtp][2 * j][3] + b01;
                float w0 = acc1[mtp][2 * j + 1][0] + b10;
                float w1 = acc1[mtp][2 * j + 1][1] + b11;
                float w2 = acc1[mtp][2 * j + 1][2] + b10;
                float w3 = acc1[mtp][2 * j + 1][3] + b11;
                v0 /= (1.0f + __expf(-v0)); v1 /= (1.0f + __expf(-v1));
                v2 /= (1.0f + __expf(-v2)); v3 /= (1.0f + __expf(-v3));
                w0 /= (1.0f + __expf(-w0)); w1 /= (1.0f + __expf(-w1));
                w2 /= (1.0f + __expf(-w2)); w3 /= (1.0f + __expf(-w3));
                uint4 hv;
                hv.x = pack2h(v0, v1); hv.y = pack2h(v2, v3);
                hv.z = pack2h(w0, w1); hv.w = pack2h(w2, w3);
                const uint32_t hb = (uint32_t)(((mband * 2 + mtp) * 16 + kq) * 512) + (uint32_t)lane * 16;
                *(uint4*)(smem + SM_R + hb) = hv;
            }
        }

        // ===== GEMM2: 4 phases of k=64 =====
#pragma unroll 1
        for (int p = 0; p < 4; p++) {
            const char* Wq;
            if (c == 0) {
                const int bsel = p & 1;      // A for p=0,2 ; B for p=1,3
                if (tid == 0) {
                    if (bsel) { MBAR_WAIT(sb + 24, pwb); pwb ^= 1; }
                    else      { MBAR_WAIT(sb + 16, pwa); pwa ^= 1; }
                }
                __syncthreads();   // quarter visible; phase p-1 MMAs done; p==0: H visible
                if (tid == 0 && (p == 1 || p == 2)) {   // p=1: q2->A ; p=2: q3->B
                    uint32_t bar = sb + ((p == 1) ? 16 : 24);
                    uint32_t dst = sb + SM_R + 32768 + ((p == 1) ? 0 : 16384);
                    MBAR_EXPECT(bar, 16384);
                    bulk_g2s(dst, g_W2p + (size_t)(1 + p) * 16384, 16384, bar);
                }
                Wq = smem + SM_R + 32768 + bsel * 16384;
            } else {
                // c==1: quarters all resident; waits only at p0 (A: q4+q6) and p1 (B: q5+q7)
                if (p == 0) {
                    if (tid == 0) { MBAR_WAIT(sb + 16, pwa); pwa ^= 1; }
                    __syncthreads();   // also publishes H
                } else if (p == 1) {
                    if (tid == 0) { MBAR_WAIT(sb + 24, pwb); pwb ^= 1; }
                    __syncthreads();
                }
                Wq = (p == 0) ? (smem + SM_R + 32768)
                   : (p == 1) ? (smem + SM_R + 49152)
                   : (p == 2) ? (smem + SM_A)
                              : (smem + SM_A + 16384);
            }
#pragma unroll
            for (int kt = 0; kt < 4; kt++) {
                const int st = p * 4 + kt;
                uint4 ah0 = *(const uint4*)(smem + SM_R + (uint32_t)(((mband * 2) * 16 + st) * 512) + (uint32_t)lane * 16);
                uint4 ah1 = *(const uint4*)(smem + SM_R + (uint32_t)(((mband * 2 + 1) * 16 + st) * 512) + (uint32_t)lane * 16);
#pragma unroll
                for (int np = 0; np < 2; np++) {
                    uint4 Bv = *(const uint4*)(Wq + (uint32_t)(((kt * 8 + nband * 2 + np) * 32 + lane) * 16));
                    mma_f16(acc2[0][np * 2],     ah0, Bv.x, Bv.y);
                    mma_f16(acc2[1][np * 2],     ah1, Bv.x, Bv.y);
                    mma_f16(acc2[0][np * 2 + 1], ah0, Bv.z, Bv.w);
                    mma_f16(acc2[1][np * 2 + 1], ah1, Bv.z, Bv.w);
                }
            }
        }
        __syncthreads();   // GEMM2 done: all buffers free
        if (tid == 0 && c == 0) {          // next chunk's W1 tile 0 -> buf0
            MBAR_EXPECT(sb + 0, 32768);
            bulk_g2s(sb + SM_R, g_W1p + (size_t)6 * 32768, 32768, sb + 0);
        }
        // reset acc1 for next chunk
#pragma unroll
        for (int a = 0; a < 2; a++)
#pragma unroll
            for (int b = 0; b < 8; b++)
#pragma unroll
                for (int cc = 0; cc < 4; cc++) acc1[a][b][cc] = 0.f;
    }

    // ===== epilogue: stage acc2+b2 (overlay A region), LayerNorm, +edge, store =====
    float* stg = (float*)(smem + SM_A);   // 64 x 130 fp32 (after final sync above)
#pragma unroll
    for (int ntp = 0; ntp < 4; ntp++) {
        int col = nband * 32 + ntp * 8 + (lane & 3) * 2;
        float bb0 = b2[col], bb1 = b2[col + 1];
#pragma unroll
        for (int mtp = 0; mtp < 2; mtp++) {
            int row = mband * 32 + mtp * 16 + (lane >> 2);
            float2 v0 = make_float2(acc2[mtp][ntp][0] + bb0, acc2[mtp][ntp][1] + bb1);
            float2 v1 = make_float2(acc2[mtp][ntp][2] + bb0, acc2[mtp][ntp][3] + bb1);
            *(float2*)(stg + row * 130 + col)       = v0;
            *(float2*)(stg + (row + 8) * 130 + col) = v1;
        }
    }
    __syncthreads();
    if (tid < MROWS) {
        float* rp = stg + tid * 130;
        float s = 0.f, qq = 0.f;
#pragma unroll
        for (int j = 0; j < 128; j += 2) {
            float2 v = *(float2*)(rp + j);
            s += v.x + v.y;
            qq += v.x * v.x + v.y * v.y;
        }
        float mu = s * (1.0f / 128.0f);
        float var = qq * (1.0f / 128.0f) - mu * mu;
        float rs = rsqrtf(var + 1e-5f);
#pragma unroll
        for (int j = 0; j < 128; j += 2) {
            float2 v = *(float2*)(rp + j);
            float2 g = *(const float2*)(gamma + j);
            float2 b = *(const float2*)(beta + j);
            v.x = (v.x - mu) * rs * g.x + b.x;
            v.y = (v.y - mu) * rs * g.y + b.y;
            *(float2*)(rp + j) = v;
        }
    }
    __syncthreads();
#pragma unroll
    for (int it = 0; it < 8; it++) {
        int idx = tid + it * NTH;
        int r = idx >> 5, c4 = idx & 31;
        float2 u0 = *(float2*)(stg + r * 130 + c4 * 4);
        float2 u1 = *(float2*)(stg + r * 130 + c4 * 4 + 2);
        float4 e = *(const float4*)(edge + (size_t)(row0 + r) * 128 + c4 * 4);
        float4 o = make_float4(u0.x + e.x, u0.y + e.y, u1.x + e.z, u1.y + e.w);
        *(float4*)(out + (size_t)(row0 + r) * 128 + c4 * 4) = o;
    }
}

extern "C" void kernel_launch(void* const* d_in, const int* in_sizes, int n_in,
                              void* d_out, int out_size)
{
    const float* x_i   = (const float*)d_in[0];
    const float* x_j   = (const float*)d_in[1];
    const float* edge  = (const float*)d_in[2];
    const float* W1    = (const float*)d_in[3];
    const float* b1    = (const float*)d_in[4];
    const float* W2    = (const float*)d_in[5];
    const float* b2    = (const float*)d_in[6];
    const float* gamma = (const float*)d_in[7];
    const float* beta  = (const float*)d_in[8];
    float* out = (float*)d_out;

    cudaFuncSetAttribute(edge_mlp_hmma, cudaFuncAttributeMaxDynamicSharedMemorySize, SM_TOT);

    pack_w<<<512, 256>>>(W1, W2);
    edge_mlp_hmma<<<NCTA, NTH, SM_TOT>>>(x_i, x_j, edge, b1, b2, gamma, beta, out);
}